// round 12
// baseline (speedup 1.0000x reference)
#include <cuda_runtime.h>
#include <cuda_bf16.h>
#include <float.h>

#define IMG_W   2048
#define IMG_H   2048
#define WM1     2047.0f
#define TPB     128
#define BUILD_TPB 256
#define MAXBLK  4096
#define SPLIT   4          // threads per point
#define G       5          // queue depth (loads in flight per thread)
#define QSCALE  65535.0f
#define QINV    (1.0f / 65535.0f)

// u16 quad table: tab[y*2048+x] = round(65535 * {img[y][x], img[y][x1], img[y1][x], img[y1][x1]})
__device__ ushort4 g_tab[IMG_W * IMG_H];         // 32 MB -> L2-resident with img
__device__ float g_partials[MAXBLK];
__device__ unsigned int g_count;                 // zero-init; wraps via atomicInc

__device__ __forceinline__ unsigned short quant(float v) {
    return (unsigned short)min(__float2uint_rn(v * QSCALE), 65535u);
}

__global__ void __launch_bounds__(BUILD_TPB)
build_tab_kernel(const float* __restrict__ img) {
    int tid = blockIdx.x * BUILD_TPB + threadIdx.x;
    int y  = tid >> 9;
    int xg = (tid & 511) << 2;
    int y1 = min(y + 1, IMG_H - 1);
    const float4* r0v = (const float4*)(img + y  * IMG_W);
    const float4* r1v = (const float4*)(img + y1 * IMG_W);
    float4 a = __ldg(&r0v[xg >> 2]);
    float4 c = __ldg(&r1v[xg >> 2]);
    int x4 = min(xg + 4, IMG_W - 1);
    float a4 = __ldg(img + y  * IMG_W + x4);
    float c4 = __ldg(img + y1 * IMG_W + x4);
    ushort4* dst = &g_tab[y * IMG_W + xg];
    dst[0] = make_ushort4(quant(a.x), quant(a.y), quant(c.x), quant(c.y));
    dst[1] = make_ushort4(quant(a.y), quant(a.z), quant(c.y), quant(c.z));
    dst[2] = make_ushort4(quant(a.z), quant(a.w), quant(c.z), quant(c.w));
    dst[3] = make_ushort4(quant(a.w), quant(a4),  quant(c.w), quant(c4));
}

// coords must be pre-clamped to [0, 2047]
__device__ __forceinline__ ushort4 quad_at(float x, float y) {
    int idx = (int)fmaf(truncf(y), 2048.0f, truncf(x));   // exact (< 2^22)
    return __ldg(&g_tab[idx]);
}

// interpolated value in u16 units (scale deferred to the end)
__device__ __forceinline__ float interp(ushort4 q, float x, float y) {
    float wx = x - truncf(x);
    float wy = y - truncf(y);
    float qa = (float)q.x, qb = (float)q.y, qc = (float)q.z, qd = (float)q.w;
    float omwx = 1.0f - wx;
    float top = qa * omwx + qb * wx;
    float bot = qc * omwx + qd * wx;
    return top * (1.0f - wy) + bot * wy;
}

__global__ void __launch_bounds__(TPB)
contour_loss_kernel(const float* __restrict__ points,
                    const float* __restrict__ normals,
                    float* __restrict__ out,
                    int N, int nblocks, float inv_n) {
    int gtid = blockIdx.x * TPB + threadIdx.x;
    int pt  = gtid >> 2;        // point index
    int sub = gtid & 3;         // segment index within point
    float sq = 0.0f;

    if (pt < N) {
        float px = fminf(fmaxf(__ldg(&points[2 * pt]),     0.0f), WM1);
        float py = fminf(fmaxf(__ldg(&points[2 * pt + 1]), 0.0f), WM1);
        float nx = __ldg(&normals[2 * pt]);
        float ny = __ldg(&normals[2 * pt + 1]);
        float dx = -ny, dy = nx;
        float inv = rsqrtf(dx * dx + dy * dy);
        dx *= inv; dy *= inv;

        float t_left  = (dx != 0.0f) ? (0.0f - px) / dx : -FLT_MAX;
        float t_right = (dx != 0.0f) ? (WM1  - px) / dx :  FLT_MAX;
        float t_top   = (dy != 0.0f) ? (0.0f - py) / dy : -FLT_MAX;
        float t_bot   = (dy != 0.0f) ? (WM1  - py) / dy :  FLT_MAX;
        float t_min = fmaxf(t_left,  t_top);
        float t_max = fminf(t_right, t_bot);

        float p1x = fmaf(t_min, dx, px), p1y = fmaf(t_min, dy, py);
        float p2x = fmaf(t_max, dx, px), p2y = fmaf(t_max, dy, py);
        float vx = p2x - p1x, vy = p2y - p1y;

        const float step = 1.0f / 99.0f;

        int c_lo = 1 + sub * 25;                 // first center this thread owns
        int c_hi = min(c_lo + 24, 98);           // last real center (sub3: 98)

        // clamped sample coords (clamps are load-bearing: for ~25% of points
        // the t-interval is inverted and raw coords are far outside the image;
        // the reference clips every sample coordinate — so do we).
        #define CL(v)     fminf(fmaxf((v), 0.0f), WM1)
        #define SX(s)     CL(fmaf((float)(s) * step, vx, p1x))
        #define SY(s)     CL(fmaf((float)(s) * step, vy, p1y))
        // phantom samples (s > 99, sub 3 only): t up to ~1.07 overshoots p2;
        // coords clamp to the border (valid addresses, values feed only gated
        // windows).

        // prologue: ref + samples c_lo-1, c_lo + queue fill (8 LDGs in flight)
        ushort4 qr = quad_at(px, py);
        float ax0 = SX(c_lo - 1), ay0 = SY(c_lo - 1);
        ushort4 q0 = quad_at(ax0, ay0);
        float cx  = SX(c_lo),     cy  = SY(c_lo);
        ushort4 q1 = quad_at(cx, cy);

        ushort4 q[G];
        float sxq[G], syq[G];
        #pragma unroll
        for (int j = 0; j < G; j++) {
            float sx = SX(c_lo + 1 + j), sy = SY(c_lo + 1 + j);
            sxq[j] = sx; syq[j] = sy;
            q[j] = quad_at(sx, sy);
        }

        float ref_val = interp(qr, px, py);      // u16 units
        float v_prev  = interp(q0, ax0, ay0);
        float v_cur   = interp(q1, cx, cy);

        // defaults: sub 0 carries vals[1] (argmin of all-inf -> idx 0 -> vals[1])
        float best_dist = FLT_MAX;
        int   best_idx  = (sub == 0) ? 0x7FFFFFFE : 0x7FFFFFFF;
        float best_val  = (sub == 0) ? v_cur : 0.0f;

        // rotating depth-5 queue: consume slot j, immediately refill it with
        // the sample 5 ahead (coords computed ONCE, stored). Groups 0-3 refill;
        // group 4 is consume-only.
        for (int g = 0; g < 4; g++) {            // rolled (R8 lesson)
            int base = c_lo + 1 + g * G;
            #pragma unroll
            for (int j = 0; j < G; j++) {
                float ax = sxq[j], ay = syq[j];
                float v_next = interp(q[j], ax, ay);
                int s = base + j - 1;            // center being tested
                if (v_cur < v_prev && v_cur < v_next && s <= c_hi) {
                    float ddx = cx - px, ddy = cy - py;
                    float dist = sqrtf(ddx * ddx + ddy * ddy);
                    if (dist < best_dist) {      // ascending s + strict < = first min
                        best_dist = dist;
                        best_idx  = s;
                        best_val  = v_cur;
                    }
                }
                v_prev = v_cur;
                v_cur  = v_next;
                cx = ax; cy = ay;
                // refill slot j with sample base+5+j (next group's j-th)
                float sx = SX(base + G + j), sy = SY(base + G + j);
                sxq[j] = sx; syq[j] = sy;
                q[j] = quad_at(sx, sy);
            }
        }
        {   // epilogue group (g = 4): consume only
            int base = c_lo + 1 + 4 * G;
            #pragma unroll
            for (int j = 0; j < G; j++) {
                float ax = sxq[j], ay = syq[j];
                float v_next = interp(q[j], ax, ay);
                int s = base + j - 1;
                if (v_cur < v_prev && v_cur < v_next && s <= c_hi) {
                    float ddx = cx - px, ddy = cy - py;
                    float dist = sqrtf(ddx * ddx + ddy * ddy);
                    if (dist < best_dist) {
                        best_dist = dist;
                        best_idx  = s;
                        best_val  = v_cur;
                    }
                }
                v_prev = v_cur;
                v_cur  = v_next;
                cx = ax; cy = ay;
            }
        }
        #undef CL
        #undef SX
        #undef SY

        // combine across the 4 sub-threads (lexicographic on (dist, idx))
        #pragma unroll
        for (int m = 1; m <= 2; m <<= 1) {
            float od = __shfl_xor_sync(0xFFFFFFFFu, best_dist, m);
            int   oi = __shfl_xor_sync(0xFFFFFFFFu, best_idx,  m);
            float ov = __shfl_xor_sync(0xFFFFFFFFu, best_val,  m);
            if (od < best_dist || (od == best_dist && oi < best_idx)) {
                best_dist = od; best_idx = oi; best_val = ov;
            }
        }

        if (sub == 0) {
            float diff = (best_val - ref_val) * QINV;   // scale once
            sq = diff * diff;
        }
    }

    // ── block reduction (deterministic) ──
    __shared__ float smem[TPB / 32];
    __shared__ bool s_last;
    float v = sq;
    #pragma unroll
    for (int off = 16; off > 0; off >>= 1)
        v += __shfl_down_sync(0xFFFFFFFFu, v, off);
    int lane = threadIdx.x & 31;
    int wid  = threadIdx.x >> 5;
    if (lane == 0) smem[wid] = v;
    __syncthreads();
    if (wid == 0) {
        v = (lane < TPB / 32) ? smem[lane] : 0.0f;
        #pragma unroll
        for (int off = 2; off > 0; off >>= 1)
            v += __shfl_down_sync(0xFFFFFFFFu, v, off);
        if (lane == 0) {
            g_partials[blockIdx.x] = v;
            __threadfence();
            unsigned int t = atomicInc(&g_count, (unsigned int)(nblocks - 1));
            s_last = (t == (unsigned int)(nblocks - 1));
        }
    }
    __syncthreads();

    if (s_last) {
        float acc = 0.0f;
        for (int k = threadIdx.x; k < nblocks; k += TPB)
            acc += g_partials[k];
        #pragma unroll
        for (int off = 16; off > 0; off >>= 1)
            acc += __shfl_down_sync(0xFFFFFFFFu, acc, off);
        if (lane == 0) smem[wid] = acc;
        __syncthreads();
        if (wid == 0) {
            acc = (lane < TPB / 32) ? smem[lane] : 0.0f;
            #pragma unroll
            for (int off = 2; off > 0; off >>= 1)
                acc += __shfl_down_sync(0xFFFFFFFFu, acc, off);
            if (lane == 0) out[0] = acc * inv_n;
        }
    }
}

extern "C" void kernel_launch(void* const* d_in, const int* in_sizes, int n_in,
                              void* d_out, int out_size) {
    const float* img     = (const float*)d_in[0];
    const float* points  = (const float*)d_in[1];
    const float* normals = (const float*)d_in[2];
    float* out = (float*)d_out;

    int N = in_sizes[1] / 2;
    int total = N * SPLIT;
    int blocks = (total + TPB - 1) / TPB;

    build_tab_kernel<<<(IMG_W * (IMG_W / 4)) / BUILD_TPB, BUILD_TPB>>>(img);
    contour_loss_kernel<<<blocks, TPB>>>(points, normals, out, N, blocks,
                                         1.0f / (float)N);
}

// round 13
// speedup vs baseline: 1.1394x; 1.1394x over previous
#include <cuda_runtime.h>
#include <cuda_bf16.h>
#include <float.h>

#define IMG_W   2048
#define IMG_H   2048
#define WM1     2047.0f
#define TPB     128
#define BUILD_TPB 256
#define MAXBLK  4096
#define SPLIT   4          // threads per point
#define G       5          // loads batched per group
#define QSCALE  65535.0f
#define QINV    (1.0f / 65535.0f)

// u16 quad table: tab[y*2048+x] = round(65535 * {img[y][x], img[y][x1], img[y1][x], img[y1][x1]})
__device__ ushort4 g_tab[IMG_W * IMG_H];         // 32 MB -> L2-resident with img
__device__ float g_partials[MAXBLK];
__device__ unsigned int g_count;                 // zero-init; wraps via atomicInc

__device__ __forceinline__ unsigned short quant(float v) {
    return (unsigned short)min(__float2uint_rn(v * QSCALE), 65535u);
}

__global__ void __launch_bounds__(BUILD_TPB)
build_tab_kernel(const float* __restrict__ img) {
    int tid = blockIdx.x * BUILD_TPB + threadIdx.x;
    int y  = tid >> 9;
    int xg = (tid & 511) << 2;
    int y1 = min(y + 1, IMG_H - 1);
    const float4* r0v = (const float4*)(img + y  * IMG_W);
    const float4* r1v = (const float4*)(img + y1 * IMG_W);
    float4 a = __ldg(&r0v[xg >> 2]);
    float4 c = __ldg(&r1v[xg >> 2]);
    int x4 = min(xg + 4, IMG_W - 1);
    float a4 = __ldg(img + y  * IMG_W + x4);
    float c4 = __ldg(img + y1 * IMG_W + x4);
    ushort4* dst = &g_tab[y * IMG_W + xg];
    dst[0] = make_ushort4(quant(a.x), quant(a.y), quant(c.x), quant(c.y));
    dst[1] = make_ushort4(quant(a.y), quant(a.z), quant(c.y), quant(c.z));
    dst[2] = make_ushort4(quant(a.z), quant(a.w), quant(c.z), quant(c.w));
    dst[3] = make_ushort4(quant(a.w), quant(a4),  quant(c.w), quant(c4));
}

// coords must be pre-clamped to [0, 2047]
__device__ __forceinline__ ushort4 quad_at(float x, float y) {
    int idx = (int)fmaf(truncf(y), 2048.0f, truncf(x));   // exact (< 2^22)
    return __ldg(&g_tab[idx]);
}

// interpolated value in u16 units (scale deferred to the end)
__device__ __forceinline__ float interp(ushort4 q, float x, float y) {
    float wx = x - truncf(x);
    float wy = y - truncf(y);
    float qa = (float)q.x, qb = (float)q.y, qc = (float)q.z, qd = (float)q.w;
    float omwx = 1.0f - wx;
    float top = qa * omwx + qb * wx;
    float bot = qc * omwx + qd * wx;
    return top * (1.0f - wy) + bot * wy;
}

__global__ void __launch_bounds__(TPB)
contour_loss_kernel(const float* __restrict__ points,
                    const float* __restrict__ normals,
                    float* __restrict__ out,
                    int N, int nblocks, float inv_n) {
    int gtid = blockIdx.x * TPB + threadIdx.x;
    int pt  = gtid >> 2;        // point index
    int sub = gtid & 3;         // segment index within point
    int ptc = min(pt, N - 1);   // all lanes stay active (shuffle safety)
    bool valid = (pt < N);

    float px = fminf(fmaxf(__ldg(&points[2 * ptc]),     0.0f), WM1);
    float py = fminf(fmaxf(__ldg(&points[2 * ptc + 1]), 0.0f), WM1);
    float nx = __ldg(&normals[2 * ptc]);
    float ny = __ldg(&normals[2 * ptc + 1]);
    float dx = -ny, dy = nx;
    float inv = rsqrtf(dx * dx + dy * dy);
    dx *= inv; dy *= inv;

    float t_left  = (dx != 0.0f) ? (0.0f - px) / dx : -FLT_MAX;
    float t_right = (dx != 0.0f) ? (WM1  - px) / dx :  FLT_MAX;
    float t_top   = (dy != 0.0f) ? (0.0f - py) / dy : -FLT_MAX;
    float t_bot   = (dy != 0.0f) ? (WM1  - py) / dy :  FLT_MAX;
    float t_min = fmaxf(t_left,  t_top);
    float t_max = fminf(t_right, t_bot);

    float p1x = fmaf(t_min, dx, px), p1y = fmaf(t_min, dy, py);
    float p2x = fmaf(t_max, dx, px), p2y = fmaf(t_max, dy, py);
    float vx = p2x - p1x, vy = p2y - p1y;

    const float step = 1.0f / 99.0f;
    int s0 = sub * 25;          // this thread owns samples [s0, s0+24]

    // clamped sample coords (clamps are load-bearing: for ~25% of points the
    // t-interval is inverted and raw coords lie far outside the image; the
    // reference clips every sample coordinate).
    #define CL(v)  fminf(fmaxf((v), 0.0f), WM1)
    #define SX(s)  CL(fmaf((float)(s) * step, vx, p1x))
    #define SY(s)  CL(fmaf((float)(s) * step, vy, p1y))

    // ref sample: only sub 0 (others' copies were redundant loads)
    float ref_val = 0.0f;
    if (sub == 0) {
        ushort4 qr = quad_at(px, py);
        ref_val = interp(qr, px, py);
    }

    // prologue: first group's 5 loads in flight
    ushort4 qA[G], qB[G];
    #pragma unroll
    for (int j = 0; j < G; j++)
        qA[j] = quad_at(SX(s0 + j), SY(s0 + j));

    float v_prev = 0.0f, v_cur = 0.0f, cx = 0.0f, cy = 0.0f;
    float v_first = 0.0f, v_second = 0.0f, cfx = 0.0f, cfy = 0.0f;

    float best_dist = FLT_MAX;
    int   best_idx  = (sub == 0) ? 0x7FFFFFFE : 0x7FFFFFFF;
    float best_val  = 0.0f;

    // 5 groups x 5 samples, double-buffered (R10 structure: coords recomputed
    // bit-identically at consume -> no stored coord arrays, regs stay low).
    for (int g = 0; g < 5; g++) {               // rolled (R8/R12 lesson)
        if (g < 4) {
            int nb = s0 + (g + 1) * G;
            #pragma unroll
            for (int j = 0; j < G; j++)
                qB[j] = quad_at(SX(nb + j), SY(nb + j));
        }
        int kbase = g * G;
        #pragma unroll
        for (int j = 0; j < G; j++) {
            int k = kbase + j;                   // local sample index 0..24
            float ax = SX(s0 + k);
            float ay = SY(s0 + k);
            float vn = interp(qA[j], ax, ay);
            if (k == 0) {
                v_first = vn; cfx = ax; cfy = ay;
                v_cur = vn;
            } else {
                if (k == 1) v_second = vn;
                if (k >= 2 && v_cur < v_prev && v_cur < vn) {
                    // interior window center k-1 (global s0+k-1); coords (cx,cy)
                    float ddx = cx - px, ddy = cy - py;
                    float dist = sqrtf(ddx * ddx + ddy * ddy);
                    if (dist < best_dist) {      // ascending + strict < = first min
                        best_dist = dist;
                        best_idx  = s0 + k - 1;
                        best_val  = v_cur;
                    }
                }
                v_prev = v_cur;
                v_cur  = vn;
            }
            cx = ax; cy = ay;
        }
        #pragma unroll
        for (int j = 0; j < G; j++)
            qA[j] = qB[j];
    }
    #undef CL
    #undef SX
    #undef SY

    // boundary values from neighbor subs (same warp, adjacent lanes)
    float nb_last  = __shfl_up_sync(0xFFFFFFFFu, v_cur, 1);    // prev sub's v[24]
    float nb_first = __shfl_down_sync(0xFFFFFFFFu, v_first, 1);// next sub's v[0]

    // left-boundary window: center s0 (sub>0): (nb_last, v_first, v_second)
    if (sub > 0 && v_first < nb_last && v_first < v_second) {
        float ddx = cfx - px, ddy = cfy - py;
        float dist = sqrtf(ddx * ddx + ddy * ddy);
        if (dist < best_dist || (dist == best_dist && s0 < best_idx)) {
            best_dist = dist; best_idx = s0; best_val = v_first;
        }
    }
    // right-boundary window: center s0+24 (sub<3): (v_prev, v_cur, nb_first)
    if (sub < 3 && v_cur < v_prev && v_cur < nb_first) {
        float ddx = cx - px, ddy = cy - py;
        float dist = sqrtf(ddx * ddx + ddy * ddy);
        if (dist < best_dist || (dist == best_dist && (s0 + 24) < best_idx)) {
            best_dist = dist; best_idx = s0 + 24; best_val = v_cur;
        }
    }
    // all-inf default: argmin -> 0 -> vals[1] = global sample 1 = sub0's v_second
    if (sub == 0 && best_idx == 0x7FFFFFFE) best_val = v_second;

    // combine across the 4 sub-threads (lexicographic on (dist, idx))
    #pragma unroll
    for (int m = 1; m <= 2; m <<= 1) {
        float od = __shfl_xor_sync(0xFFFFFFFFu, best_dist, m);
        int   oi = __shfl_xor_sync(0xFFFFFFFFu, best_idx,  m);
        float ov = __shfl_xor_sync(0xFFFFFFFFu, best_val,  m);
        if (od < best_dist || (od == best_dist && oi < best_idx)) {
            best_dist = od; best_idx = oi; best_val = ov;
        }
    }

    float sq = 0.0f;
    if (valid && sub == 0) {
        float diff = (best_val - ref_val) * QINV;   // scale once
        sq = diff * diff;
    }

    // ── block reduction (deterministic) ──
    __shared__ float smem[TPB / 32];
    __shared__ bool s_last;
    float v = sq;
    #pragma unroll
    for (int off = 16; off > 0; off >>= 1)
        v += __shfl_down_sync(0xFFFFFFFFu, v, off);
    int lane = threadIdx.x & 31;
    int wid  = threadIdx.x >> 5;
    if (lane == 0) smem[wid] = v;
    __syncthreads();
    if (wid == 0) {
        v = (lane < TPB / 32) ? smem[lane] : 0.0f;
        #pragma unroll
        for (int off = 2; off > 0; off >>= 1)
            v += __shfl_down_sync(0xFFFFFFFFu, v, off);
        if (lane == 0) {
            g_partials[blockIdx.x] = v;
            __threadfence();
            unsigned int t = atomicInc(&g_count, (unsigned int)(nblocks - 1));
            s_last = (t == (unsigned int)(nblocks - 1));
        }
    }
    __syncthreads();

    if (s_last) {
        float acc = 0.0f;
        for (int k = threadIdx.x; k < nblocks; k += TPB)
            acc += g_partials[k];
        #pragma unroll
        for (int off = 16; off > 0; off >>= 1)
            acc += __shfl_down_sync(0xFFFFFFFFu, acc, off);
        if (lane == 0) smem[wid] = acc;
        __syncthreads();
        if (wid == 0) {
            acc = (lane < TPB / 32) ? smem[lane] : 0.0f;
            #pragma unroll
            for (int off = 2; off > 0; off >>= 1)
                acc += __shfl_down_sync(0xFFFFFFFFu, acc, off);
            if (lane == 0) out[0] = acc * inv_n;
        }
    }
}

extern "C" void kernel_launch(void* const* d_in, const int* in_sizes, int n_in,
                              void* d_out, int out_size) {
    const float* img     = (const float*)d_in[0];
    const float* points  = (const float*)d_in[1];
    const float* normals = (const float*)d_in[2];
    float* out = (float*)d_out;

    int N = in_sizes[1] / 2;
    int total = N * SPLIT;
    int blocks = (total + TPB - 1) / TPB;

    build_tab_kernel<<<(IMG_W * (IMG_W / 4)) / BUILD_TPB, BUILD_TPB>>>(img);
    contour_loss_kernel<<<blocks, TPB>>>(points, normals, out, N, blocks,
                                         1.0f / (float)N);
}